// round 12
// baseline (speedup 1.0000x reference)
#include <cuda_runtime.h>
#include <cuda_fp16.h>
#include <stdint.h>

// ============================================================================
// GPT block, sm_100-safe mma.sync. fp16 hi-legs + int8 (2x rate) lo-legs.
//   QKV   : fused 3-pass fp16 GEMM (Q,K pair out; V fp32 out)
//   scores: S = q8h*k8l + q8l*k8h (int8) + Qh*Kh (fp16 accumulate)
//   attn@V/FFN1/FFN2: int8 lo-leg -> fp32 scratch, fp16 hi-leg accumulates
// ============================================================================

typedef __half h16;

// ---------------- helpers ----------------
__device__ __forceinline__ uint32_t smem_u32(const void* p) {
    uint32_t a;
    asm("{ .reg .u64 t; cvta.to.shared.u64 t, %1; cvt.u32.u64 %0, t; }"
        : "=r"(a) : "l"(p));
    return a;
}
__device__ __forceinline__ void cp16(uint32_t saddr, const void* g) {
    asm volatile("cp.async.cg.shared.global [%0], [%1], 16;"
                 :: "r"(saddr), "l"(g) : "memory");
}
#define CP_COMMIT() asm volatile("cp.async.commit_group;" ::: "memory")
#define CP_WAIT1()  asm volatile("cp.async.wait_group 1;" ::: "memory")

__device__ __forceinline__ void ldsm4(uint32_t* r, uint32_t a) {
    asm volatile("ldmatrix.sync.aligned.m8n8.x4.shared.b16 {%0,%1,%2,%3}, [%4];"
                 : "=r"(r[0]), "=r"(r[1]), "=r"(r[2]), "=r"(r[3]) : "r"(a));
}
__device__ __forceinline__ void mma16816(float* c, const uint32_t* a,
                                         const uint32_t* b) {
    asm volatile(
        "mma.sync.aligned.m16n8k16.row.col.f32.f16.f16.f32 "
        "{%0,%1,%2,%3}, {%4,%5,%6,%7}, {%8,%9}, {%0,%1,%2,%3};"
        : "+f"(c[0]), "+f"(c[1]), "+f"(c[2]), "+f"(c[3])
        : "r"(a[0]), "r"(a[1]), "r"(a[2]), "r"(a[3]), "r"(b[0]), "r"(b[1]));
}
__device__ __forceinline__ void mma_s8(int* c, const uint32_t* a,
                                       const uint32_t* b) {
    asm volatile(
        "mma.sync.aligned.m16n8k32.row.col.s32.s8.s8.s32 "
        "{%0,%1,%2,%3}, {%4,%5,%6,%7}, {%8,%9}, {%0,%1,%2,%3};"
        : "+r"(c[0]), "+r"(c[1]), "+r"(c[2]), "+r"(c[3])
        : "r"(a[0]), "r"(a[1]), "r"(a[2]), "r"(a[3]), "r"(b[0]), "r"(b[1]));
}

// XOR swizzle: 16B chunk at (row, seg) of a 64B-row tile.
__device__ __forceinline__ uint32_t swz(int r, int s) {
    return (uint32_t)(r * 64 + ((s ^ ((r >> 1) & 3)) << 4));
}
__device__ __forceinline__ void split2h(float v, h16& h, h16& l) {
    h = __float2half(v);
    l = __float2half(v - __half2float(h));
}

// ---------------- scratch ----------------
__device__ h16 g_Xh[16384LL * 768], g_Xl[16384LL * 768];
__device__ h16 g_Wch[2304LL * 768], g_Wcl[2304LL * 768];
__device__ h16 g_W1s[3072 * 768];
__device__ h16 g_W2s[768 * 3072];
__device__ h16 g_Qh[4LL * 4096 * 768], g_Ql[4LL * 4096 * 768];
__device__ h16 g_Kh[4LL * 4096 * 768], g_Kl[4LL * 4096 * 768];
__device__ float g_Vf[4LL * 4096 * 768];
__device__ h16 g_VTs[4LL * 768 * 4096];
__device__ float g_S[4LL * 4096 * 4096];     // scores, then reused as fp32 scratch
__device__ h16 g_Ph[4LL * 4096 * 4096], g_Pl[4LL * 4096 * 4096];
__device__ h16 g_NVh[4LL * 4096 * 768], g_NVl[4LL * 4096 * 768];
__device__ h16 g_Hh[16384LL * 3072], g_Hl[16384LL * 3072];
__device__ char g_q8h[16384LL * 768], g_q8l[16384LL * 768];
__device__ char g_k8h[16384LL * 768], g_k8l[16384LL * 768];
__device__ float g_sqh[16384], g_sql[16384], g_skh[16384], g_skl[16384];
// int8 lo-leg operands
__device__ char g_p8[16384LL * 4096];
__device__ char g_nv8[16384LL * 768];
__device__ char g_h8[16384LL * 3072];
__device__ char g_vt8[3072LL * 4096];
__device__ char g_w18[3072 * 768];
__device__ char g_w28[768 * 3072];
__device__ float g_sp[16384], g_snv[16384], g_sh[16384];
__device__ float g_svt[3072], g_sw1[3072], g_sw2[768];

// ---------------- fp16 GEMM ----------------
static constexpr int STAGE_BYTES = 32768;
static constexpr int SMEM_TOTAL  = 3 * STAGE_BYTES;

// OM: 0 = f32 store, 1 = pair store, 2 = f32 accumulate(in-place), 3 = QKV route
template <int PASSES>
__device__ __forceinline__ void load_stage(
    uint32_t so, int tid,
    const h16* __restrict__ Ah, const h16* __restrict__ Al,
    const h16* __restrict__ Bh, const h16* __restrict__ Bl,
    long long k0, int K)
{
    const int r = tid & 127, h = tid >> 7;
#pragma unroll
    for (int u = 0; u < 2; ++u) {
        const uint32_t d = swz(r, h * 2 + u);
        const long long g = (long long)r * K + k0 + (h * 2 + u) * 8;
        cp16(so + d,         Ah + g);
        if (PASSES >= 2) cp16(so + 8192 + d, Al + g);
        cp16(so + 16384 + d, Bh + g);
        if (PASSES == 3)  cp16(so + 24576 + d, Bl + g);
    }
}

template <int PASSES, bool BIAS, bool RELU, int OM, bool ACC>
__global__ __launch_bounds__(256, 2)
void wm_gemm(const h16* __restrict__ Ahi, const h16* __restrict__ Alo,
             const h16* __restrict__ Bhi, const h16* __restrict__ Blo,
             const float* __restrict__ bias,
             float* __restrict__ Cf, h16* __restrict__ Chi, h16* __restrict__ Clo,
             h16* __restrict__ C2hi, h16* __restrict__ C2lo,
             const int N, const int K,
             const long long bA, const long long bB, const long long bC,
             const float* __restrict__ Cacc)
{
    extern __shared__ __align__(128) char smem[];
    const uint32_t sb = smem_u32(smem);
    const int tid = threadIdx.x;
    const int wid = tid >> 5, lane = tid & 31;
    const int wm = wid >> 1, wn = wid & 1;
    const int lj = lane >> 3, lr = lane & 7;

    const long long bm = (long long)blockIdx.y * 128;
    const long long bn = (long long)blockIdx.x * 128;

    const h16* Ah = Ahi + (long long)blockIdx.z * bA + bm * K;
    const h16* Al = (PASSES >= 2) ? (Alo + (long long)blockIdx.z * bA + bm * K) : nullptr;
    const h16* Bh = Bhi + (long long)blockIdx.z * bB + bn * K;
    const h16* Bl = (PASSES == 3) ? (Blo + (long long)blockIdx.z * bB + bn * K) : nullptr;

    float acc[2][8][4];
#pragma unroll
    for (int i = 0; i < 2; ++i)
#pragma unroll
        for (int j = 0; j < 8; ++j)
#pragma unroll
            for (int t = 0; t < 4; ++t) acc[i][j][t] = 0.0f;

    const int NC = K / 32;

    load_stage<PASSES>(sb, tid, Ah, Al, Bh, Bl, 0, K);
    CP_COMMIT();
    load_stage<PASSES>(sb + STAGE_BYTES, tid, Ah, Al, Bh, Bl, 32, K);
    CP_COMMIT();

    const int arow = wm * 32 + ((lj & 1) << 3) + lr;
    const int aseg = lj >> 1;
    const int brow = wn * 64 + ((lj >> 1) << 3) + lr;
    const int bseg = lj & 1;

    int buf = 0;
    for (int c = 0; c < NC; ++c) {
        CP_WAIT1();
        __syncthreads();
        if (c + 2 < NC) {
            int nb = buf + 2; if (nb >= 3) nb -= 3;
            load_stage<PASSES>(sb + nb * STAGE_BYTES, tid, Ah, Al, Bh, Bl,
                               (long long)(c + 2) * 32, K);
        }
        CP_COMMIT();

        const uint32_t bb = sb + buf * STAGE_BYTES;
#pragma unroll
        for (int ks = 0; ks < 2; ++ks) {
            uint32_t Afh[2][4], Afl[2][4];
#pragma unroll
            for (int mt = 0; mt < 2; ++mt) {
                const uint32_t off = swz(arow + mt * 16, ks * 2 + aseg);
                ldsm4(Afh[mt], bb + off);
                if (PASSES >= 2) ldsm4(Afl[mt], bb + 8192 + off);
            }
#pragma unroll
            for (int ntp = 0; ntp < 4; ++ntp) {
                const uint32_t off = swz(brow + ntp * 16, ks * 2 + bseg);
                uint32_t Bfh[4];
                ldsm4(Bfh, bb + 16384 + off);
                uint32_t Bfl[4];
                if (PASSES == 3) ldsm4(Bfl, bb + 24576 + off);
#pragma unroll
                for (int mt = 0; mt < 2; ++mt)
#pragma unroll
                    for (int h = 0; h < 2; ++h) {
                        float* cc = acc[mt][ntp * 2 + h];
                        mma16816(cc, Afh[mt], &Bfh[h * 2]);
                        if (PASSES >= 2) mma16816(cc, Afl[mt], &Bfh[h * 2]);
                        if (PASSES == 3) mma16816(cc, Afh[mt], &Bfl[h * 2]);
                    }
            }
        }
        ++buf; if (buf == 3) buf = 0;
    }

    // ---- epilogue ----
    const long long zC = (long long)blockIdx.z * bC;
    const int rbase = (int)bm + wm * 32 + (lane >> 2);
    const int seg   = (OM == 3) ? (int)(bn / 768) : 0;
    const int cbase = (OM == 3)
        ? ((int)bn - seg * 768 + wn * 64 + (lane & 3) * 2)
        : ((int)bn + wn * 64 + (lane & 3) * 2);
    const int cstride = (OM == 3) ? 768 : N;

#pragma unroll
    for (int mt = 0; mt < 2; ++mt)
#pragma unroll
        for (int nt = 0; nt < 8; ++nt) {
            const int col = cbase + nt * 8;
            float b0 = 0.f, b1 = 0.f;
            if (BIAS) { b0 = bias[(int)bn + wn * 64 + (lane & 3) * 2 + nt * 8];
                        b1 = bias[(int)bn + wn * 64 + (lane & 3) * 2 + nt * 8 + 1]; }
#pragma unroll
            for (int rh = 0; rh < 2; ++rh) {
                const int row = rbase + mt * 16 + rh * 8;
                float v0 = acc[mt][nt][rh * 2 + 0];
                float v1 = acc[mt][nt][rh * 2 + 1];
                const long long o = zC + (long long)row * cstride + col;
                if (ACC) {
                    const float2 t = *(const float2*)(Cacc + o);
                    v0 += t.x; v1 += t.y;
                }
                if (BIAS) { v0 += b0; v1 += b1; }
                if (RELU) { v0 = fmaxf(v0, 0.f); v1 = fmaxf(v1, 0.f); }
                if (OM == 0) {
                    float2 w; w.x = v0; w.y = v1;
                    *(float2*)(Cf + o) = w;
                } else if (OM == 1) {
                    h16 h0, l0, h1, l1;
                    split2h(v0, h0, l0); split2h(v1, h1, l1);
                    *(__half2*)(Chi + o) = __halves2half2(h0, h1);
                    *(__half2*)(Clo + o) = __halves2half2(l0, l1);
                } else if (OM == 2) {
                    float2 t = *(const float2*)(Cf + o);
                    t.x += v0; t.y += v1;
                    *(float2*)(Cf + o) = t;
                } else {  // OM == 3: fused QKV routing
                    if (seg == 0) {
                        h16 h0, l0, h1, l1;
                        split2h(v0, h0, l0); split2h(v1, h1, l1);
                        *(__half2*)(Chi + o) = __halves2half2(h0, h1);
                        *(__half2*)(Clo + o) = __halves2half2(l0, l1);
                    } else if (seg == 1) {
                        h16 h0, l0, h1, l1;
                        split2h(v0, h0, l0); split2h(v1, h1, l1);
                        *(__half2*)(C2hi + o) = __halves2half2(h0, h1);
                        *(__half2*)(C2lo + o) = __halves2half2(l0, l1);
                    } else {
                        float2 w; w.x = v0; w.y = v1;
                        *(float2*)(Cf + o) = w;
                    }
                }
            }
        }
}

// ---------------- int8 GEMM: S (=/+=) (A8@B8^T) * sa_i * sb_j ----------------
// tiles 128x128, BK=64; A row-major [M,K], B row-major [N,K]; K % 64 == 0.
static constexpr int I8_STAGE = 16384;
static constexpr int I8_SMEM  = 3 * I8_STAGE;

__device__ __forceinline__ void i8_load_stage(uint32_t so, int tid,
    const char* __restrict__ A, const char* __restrict__ B, int k0, int K)
{
    const int r = tid & 127, hf = tid >> 7;
#pragma unroll
    for (int u = 0; u < 2; ++u) {
        const int s = hf * 2 + u;
        const uint32_t d = swz(r, s);
        const long long g = (long long)r * K + k0 + s * 16;
        cp16(so + d,        A + g);
        cp16(so + 8192 + d, B + g);
    }
}

template <bool INIT>
__global__ __launch_bounds__(256, 2)
void i8_gemm(const char* __restrict__ A8, const char* __restrict__ B8,
             const float* __restrict__ sa, const float* __restrict__ sb,
             float* __restrict__ S, const int N, const int K,
             const long long bA, const long long bB, const long long bC,
             const int sAz, const int sBz)
{
    extern __shared__ __align__(128) char smem[];
    const uint32_t sbase = smem_u32(smem);
    const int tid = threadIdx.x;
    const int wid = tid >> 5, lane = tid & 31;
    const int wm = wid >> 1, wn = wid & 1;
    const int lj = lane >> 3, lr = lane & 7;
    const int z = blockIdx.z;
    const long long bm = (long long)blockIdx.y * 128;
    const long long bn = (long long)blockIdx.x * 128;

    const char* Ab = A8 + (long long)z * bA + bm * K;
    const char* Bb = B8 + (long long)z * bB + bn * K;
    const float* sav = sa + (long long)z * sAz + bm;
    const float* sbv = sb + (long long)z * sBz + bn;

    int acc[2][8][4];
#pragma unroll
    for (int i = 0; i < 2; ++i)
#pragma unroll
        for (int j = 0; j < 8; ++j)
#pragma unroll
            for (int t = 0; t < 4; ++t) acc[i][j][t] = 0;

    const int NC = K / 64;
    i8_load_stage(sbase, tid, Ab, Bb, 0, K);
    CP_COMMIT();
    i8_load_stage(sbase + I8_STAGE, tid, Ab, Bb, 64, K);
    CP_COMMIT();

    // s8 fragment order == fp16 order (R9 fix): row-block fastest for A.
    const int arow = wm * 32 + ((lj & 1) << 3) + lr;
    const int aso  = lj >> 1;
    const int brow = wn * 64 + ((lj >> 1) << 3) + lr;
    const int bso  = lj & 1;

    int buf = 0;
    for (int c = 0; c < NC; ++c) {
        CP_WAIT1();
        __syncthreads();
        if (c + 2 < NC) {
            int nb = buf + 2; if (nb >= 3) nb -= 3;
            i8_load_stage(sbase + nb * I8_STAGE, tid, Ab, Bb, (c + 2) * 64, K);
        }
        CP_COMMIT();

        const uint32_t bb = sbase + buf * I8_STAGE;
#pragma unroll
        for (int step = 0; step < 2; ++step) {
            uint32_t Af[2][4];
#pragma unroll
            for (int mt = 0; mt < 2; ++mt)
                ldsm4(Af[mt], bb + swz(arow + mt * 16, step * 2 + aso));
#pragma unroll
            for (int ntp = 0; ntp < 4; ++ntp) {
                uint32_t Bf[4];
                ldsm4(Bf, bb + 8192 + swz(brow + ntp * 16, step * 2 + bso));
#pragma unroll
                for (int mt = 0; mt < 2; ++mt)
#pragma unroll
                    for (int h = 0; h < 2; ++h)
                        mma_s8(acc[mt][ntp * 2 + h], Af[mt], &Bf[h * 2]);
            }
        }
        ++buf; if (buf == 3) buf = 0;
    }

    const int rb = wm * 32 + (lane >> 2);
    const int cb = wn * 64 + (lane & 3) * 2;
    const long long zS = (long long)z * bC;
#pragma unroll
    for (int mt = 0; mt < 2; ++mt)
#pragma unroll
        for (int rh = 0; rh < 2; ++rh) {
            const int lrw = rb + mt * 16 + rh * 8;
            const float sA = sav[lrw];
#pragma unroll
            for (int nt = 0; nt < 8; ++nt) {
                const int lc = cb + nt * 8;
                const float c0 = (float)acc[mt][nt][rh * 2 + 0] * sA * sbv[lc];
                const float c1 = (float)acc[mt][nt][rh * 2 + 1] * sA * sbv[lc + 1];
                const long long o = zS + (bm + lrw) * N + bn + lc;
                if (INIT) {
                    float2 w; w.x = c0; w.y = c1;
                    *(float2*)(S + o) = w;
                } else {
                    float2 t = *(const float2*)(S + o);
                    t.x += c0; t.y += c1;
                    *(float2*)(S + o) = t;
                }
            }
        }
}

// ---------------- per-row int8 quantization of (hi,lo) fp16 pair (L=768) ------
__global__ __launch_bounds__(256)
void quant_rows(const h16* __restrict__ Ah, const h16* __restrict__ Al,
                char* __restrict__ q8h, char* __restrict__ q8l,
                float* __restrict__ sh, float* __restrict__ sl)
{
    __shared__ float red[8][2];
    const long long row = blockIdx.x;
    const int tid = threadIdx.x, lane = tid & 31, warp = tid >> 5;
    const h16* ph = Ah + row * 768;
    const h16* pl = Al + row * 768;

    float vh[3], vl[3];
    float mh = 0.f, ml = 0.f;
#pragma unroll
    for (int i = 0; i < 3; ++i) {
        vh[i] = __half2float(ph[tid + i * 256]);
        vl[i] = __half2float(pl[tid + i * 256]);
        mh = fmaxf(mh, fabsf(vh[i]));
        ml = fmaxf(ml, fabsf(vl[i]));
    }
#pragma unroll
    for (int o = 16; o > 0; o >>= 1) {
        mh = fmaxf(mh, __shfl_xor_sync(0xffffffffu, mh, o));
        ml = fmaxf(ml, __shfl_xor_sync(0xffffffffu, ml, o));
    }
    if (lane == 0) { red[warp][0] = mh; red[warp][1] = ml; }
    __syncthreads();
    mh = red[0][0]; ml = red[0][1];
#pragma unroll
    for (int w = 1; w < 8; ++w) {
        mh = fmaxf(mh, red[w][0]);
        ml = fmaxf(ml, red[w][1]);
    }
    mh = fmaxf(mh, 1e-20f);
    ml = fmaxf(ml, 1e-20f);
    const float ih = 127.f / mh, il = 127.f / ml;
#pragma unroll
    for (int i = 0; i < 3; ++i) {
        q8h[row * 768 + tid + i * 256] = (char)__float2int_rn(vh[i] * ih);
        q8l[row * 768 + tid + i * 256] = (char)__float2int_rn(vl[i] * il);
    }
    if (tid == 0) { sh[row] = mh / 127.f; sl[row] = ml / 127.f; }
}

// ---------------- generic per-row int8 quantization (any L % 256 == 0) -------
__global__ __launch_bounds__(256)
void quant_g(const h16* __restrict__ A, char* __restrict__ q8,
             float* __restrict__ s, const int L)
{
    __shared__ float red[8];
    const long long row = blockIdx.x;
    const int tid = threadIdx.x, lane = tid & 31, warp = tid >> 5;
    const h16* p = A + row * (long long)L;

    float m = 0.f;
    for (int i = tid; i < L; i += 256)
        m = fmaxf(m, fabsf(__half2float(p[i])));
#pragma unroll
    for (int o = 16; o > 0; o >>= 1)
        m = fmaxf(m, __shfl_xor_sync(0xffffffffu, m, o));
    if (lane == 0) red[warp] = m;
    __syncthreads();
    m = red[0];
#pragma unroll
    for (int w = 1; w < 8; ++w) m = fmaxf(m, red[w]);
    m = fmaxf(m, 1e-20f);
    const float inv = 127.f / m;
    char* q = q8 + row * (long long)L;
    for (int i = tid; i < L; i += 256)
        q[i] = (char)__float2int_rn(__half2float(p[i]) * inv);
    if (tid == 0) s[row] = m / 127.f;
}

// ---------------- fp32 -> (hi,lo) fp16 ----------------
__global__ __launch_bounds__(256)
void cvt_pair(const float* __restrict__ in, h16* __restrict__ hi,
              h16* __restrict__ lo, const long long n)
{
    const long long i = ((long long)blockIdx.x * 256 + threadIdx.x) * 4;
    if (i >= n) return;
    const float4 v = *(const float4*)(in + i);
    __align__(8) h16 h[4];
    __align__(8) h16 l[4];
    split2h(v.x, h[0], l[0]); split2h(v.y, h[1], l[1]);
    split2h(v.z, h[2], l[2]); split2h(v.w, h[3], l[3]);
    *(uint2*)(hi + i) = *(const uint2*)h;
    *(uint2*)(lo + i) = *(const uint2*)l;
}

// ---------------- fp32 -> single fp16 ----------------
__global__ __launch_bounds__(256)
void cvt_single(const float* __restrict__ in, h16* __restrict__ s,
                const long long n)
{
    const long long i = ((long long)blockIdx.x * 256 + threadIdx.x) * 4;
    if (i >= n) return;
    const float4 v = *(const float4*)(in + i);
    __align__(8) h16 h[4];
    h[0] = __float2half(v.x); h[1] = __float2half(v.y);
    h[2] = __float2half(v.z); h[3] = __float2half(v.w);
    *(uint2*)(s + i) = *(const uint2*)h;
}

// ---------------- V transpose: [b,4096,768]f32 -> [b,768,4096] fp16 ----------
__global__ __launch_bounds__(256)
void transpose_cvt(const float* __restrict__ V, h16* __restrict__ Ts)
{
    __shared__ float tile[32][33];
    const int b = blockIdx.z;
    const int e0 = blockIdx.x * 32;
    const int t0 = blockIdx.y * 32;
    const float* Vb = V + (long long)b * 4096 * 768;
    h16* Tb = Ts + (long long)b * 768 * 4096;
    const int tx = threadIdx.x, ty = threadIdx.y;
#pragma unroll
    for (int j = 0; j < 32; j += 8)
        tile[ty + j][tx] = Vb[(long long)(t0 + ty + j) * 768 + e0 + tx];
    __syncthreads();
#pragma unroll
    for (int j = 0; j < 32; j += 8) {
        const long long o = (long long)(e0 + ty + j) * 4096 + t0 + tx;
        Tb[o] = __float2half(tile[tx][ty + j]);
    }
}

// ---------------- softmax (rows of 4096) -> (hi,lo) fp16 ----------------
__global__ __launch_bounds__(256)
void softmax_pair(const float* __restrict__ S, h16* __restrict__ Ph,
                  h16* __restrict__ Pl)
{
    __shared__ float red[8];
    const long long row = blockIdx.x;
    const float* p = S + row * 4096;
    const int tid = threadIdx.x, lane = tid & 31, warp = tid >> 5;

    float4 v[4];
#pragma unroll
    for (int i = 0; i < 4; ++i)
        v[i] = *(const float4*)(p + tid * 4 + i * 1024);

    float mx = -3.402823466e38f;
#pragma unroll
    for (int i = 0; i < 4; ++i)
        mx = fmaxf(mx, fmaxf(fmaxf(v[i].x, v[i].y), fmaxf(v[i].z, v[i].w)));
#pragma unroll
    for (int o = 16; o > 0; o >>= 1)
        mx = fmaxf(mx, __shfl_xor_sync(0xffffffffu, mx, o));
    if (lane == 0) red[warp] = mx;
    __syncthreads();
    float rowmax = red[0];
#pragma unroll
    for (int w = 1; w < 8; ++w) rowmax = fmaxf(rowmax, red[w]);
    __syncthreads();

    float sum = 0.0f;
#pragma unroll
    for (int i = 0; i < 4; ++i) {
        v[i].x = __expf(v[i].x - rowmax);
        v[i].y = __expf(v[i].y - rowmax);
        v[i].z = __expf(v[i].z - rowmax);
        v[i].w = __expf(v[i].w - rowmax);
        sum += (v[i].x + v[i].y) + (v[i].z + v[i].w);
    }
#pragma unroll
    for (int o = 16; o > 0; o >>= 1)
        sum += __shfl_xor_sync(0xffffffffu, sum, o);
    if (lane == 0) red[warp] = sum;
    __syncthreads();
    float rowsum = 0.0f;
#pragma unroll
    for (int w = 0; w < 8; ++w) rowsum += red[w];
    const float inv = 1.0f / rowsum;

#pragma unroll
    for (int i = 0; i < 4; ++i) {
        __align__(8) h16 h[4];
        __align__(8) h16 l[4];
        split2h(v[i].x * inv, h[0], l[0]);
        split2h(v[i].y * inv, h[1], l[1]);
        split2h(v[i].z * inv, h[2], l[2]);
        split2h(v[i].w * inv, h[3], l[3]);
        const long long o = row * 4096 + tid * 4 + i * 1024;
        *(uint2*)(Ph + o) = *(const uint2*)h;
        *(uint2*)(Pl + o) = *(const uint2*)l;
    }
}

// ---------------- host ----------------
extern "C" void kernel_launch(void* const* d_in, const int* in_sizes, int n_in,
                              void* d_out, int out_size)
{
    const float* X  = (const float*)d_in[0];
    const float* Wq = (const float*)d_in[1];
    const float* Wk = (const float*)d_in[2];
    const float* Wv = (const float*)d_in[3];
    const float* W1 = (const float*)d_in[4];
    const float* b1 = (const float*)d_in[5];
    const float* W2 = (const float*)d_in[6];
    const float* b2 = (const float*)d_in[7];
    float* out = (float*)d_out;

    h16 *Xh, *Xl, *Wch, *Wcl, *W1s, *W2s;
    h16 *Qh, *Ql, *Kh, *Kl, *VTs, *Ph, *Pl, *NVh, *NVl, *Hh, *Hl;
    float *Vf, *S, *sqh, *sql, *skh, *skl, *sp, *snv, *sh, *svt, *sw1, *sw2;
    char *q8h, *q8l, *k8h, *k8l, *p8, *nv8, *h8, *vt8, *w18, *w28;
    cudaGetSymbolAddress((void**)&Xh, g_Xh);    cudaGetSymbolAddress((void**)&Xl, g_Xl);
    cudaGetSymbolAddress((void**)&Wch, g_Wch);  cudaGetSymbolAddress((void**)&Wcl, g_Wcl);
    cudaGetSymbolAddress((void**)&W1s, g_W1s);  cudaGetSymbolAddress((void**)&W2s, g_W2s);
    cudaGetSymbolAddress((void**)&Qh, g_Qh);    cudaGetSymbolAddress((void**)&Ql, g_Ql);
    cudaGetSymbolAddress((void**)&Kh, g_Kh);    cudaGetSymbolAddress((void**)&Kl, g_Kl);
    cudaGetSymbolAddress((void**)&Vf, g_Vf);    cudaGetSymbolAddress((void**)&VTs, g_VTs);
    cudaGetSymbolAddress((void**)&S, g_S);
    cudaGetSymbolAddress((void**)&Ph, g_Ph);    cudaGetSymbolAddress((void**)&Pl, g_Pl);
    cudaGetSymbolAddress((void**)&NVh, g_NVh);  cudaGetSymbolAddress((void**)&NVl, g_NVl);
    cudaGetSymbolAddress((void**)&Hh, g_Hh);    cudaGetSymbolAddress((void**)&Hl, g_Hl);
    cudaGetSymbolAddress((void**)&q8h, g_q8h);  cudaGetSymbolAddress((void**)&q8l, g_q8l);
    cudaGetSymbolAddress((void**)&k8h, g_k8h);  cudaGetSymbolAddress((void**)&k8l, g_k8l);
    cudaGetSymbolAddress((void**)&sqh, g_sqh);  cudaGetSymbolAddress((void**)&sql, g_sql);
    cudaGetSymbolAddress((void**)&skh, g_skh);  cudaGetSymbolAddress((void**)&skl, g_skl);
    cudaGetSymbolAddress((void**)&p8, g_p8);    cudaGetSymbolAddress((void**)&nv8, g_nv8);
    cudaGetSymbolAddress((void**)&h8, g_h8);    cudaGetSymbolAddress((void**)&vt8, g_vt8);
    cudaGetSymbolAddress((void**)&w18, g_w18);  cudaGetSymbolAddress((void**)&w28, g_w28);
    cudaGetSymbolAddress((void**)&sp, g_sp);    cudaGetSymbolAddress((void**)&snv, g_snv);
    cudaGetSymbolAddress((void**)&sh, g_sh);    cudaGetSymbolAddress((void**)&svt, g_svt);
    cudaGetSymbolAddress((void**)&sw1, g_sw1);  cudaGetSymbolAddress((void**)&sw2, g_sw2);

    cudaFuncSetAttribute(wm_gemm<3, false, false, 3, false>,
                         cudaFuncAttributeMaxDynamicSharedMemorySize, SMEM_TOTAL);
    cudaFuncSetAttribute(wm_gemm<1, false, false, 2, false>,
                         cudaFuncAttributeMaxDynamicSharedMemorySize, SMEM_TOTAL);
    cudaFuncSetAttribute(wm_gemm<1, false, false, 1, true>,
                         cudaFuncAttributeMaxDynamicSharedMemorySize, SMEM_TOTAL);
    cudaFuncSetAttribute(wm_gemm<1, true, true, 1, true>,
                         cudaFuncAttributeMaxDynamicSharedMemorySize, SMEM_TOTAL);
    cudaFuncSetAttribute(wm_gemm<1, true, false, 0, true>,
                         cudaFuncAttributeMaxDynamicSharedMemorySize, SMEM_TOTAL);
    cudaFuncSetAttribute(i8_gemm<true>,
                         cudaFuncAttributeMaxDynamicSharedMemorySize, I8_SMEM);
    cudaFuncSetAttribute(i8_gemm<false>,
                         cudaFuncAttributeMaxDynamicSharedMemorySize, I8_SMEM);

    // splits (launch #5 = QKV GEMM for profiling window)
    cvt_pair<<<12288, 256>>>(X,  Xh,  Xl,  16384LL * 768);
    cvt_pair<<<576,  256>>>(Wq, Wch,              Wcl,              768LL * 768);
    cvt_pair<<<576,  256>>>(Wk, Wch + 768 * 768,  Wcl + 768 * 768,  768LL * 768);
    cvt_pair<<<576,  256>>>(Wv, Wch + 1536 * 768, Wcl + 1536 * 768, 768LL * 768);
    cvt_single<<<2304, 256>>>(W1, W1s, 3072LL * 768);

    // fused QKV: [16384,2304] = X @ Wcat^T ; Q,K pair out; V fp32 out
    wm_gemm<3, false, false, 3, false><<<dim3(18, 128, 1), 256, SMEM_TOTAL>>>(
        Xh, Xl, Wch, Wcl, nullptr, Vf, Qh, Ql, Kh, Kl, 2304, 768, 0, 0, 0, nullptr);

    quant_rows<<<16384, 256>>>(Qh, Ql, q8h, q8l, sqh, sql);
    quant_rows<<<16384, 256>>>(Kh, Kl, k8h, k8l, skh, skl);
    cvt_single<<<2304, 256>>>(W2, W2s, 768LL * 3072);
    transpose_cvt<<<dim3(24, 128, 4), dim3(32, 8)>>>(Vf, VTs);
    quant_g<<<3072, 256>>>(W1s, w18, sw1, 768);
    quant_g<<<768,  256>>>(W2s, w28, sw2, 3072);
    quant_g<<<3072, 256>>>(VTs, vt8, svt, 4096);

    // scores: int8 corrections then fp16 hi-pass accumulate (in-place S)
    i8_gemm<true><<<dim3(32, 32, 4), 256, I8_SMEM>>>(
        q8h, k8l, sqh, skl, S, 4096, 768,
        4096LL * 768, 4096LL * 768, 4096LL * 4096, 4096, 4096);
    i8_gemm<false><<<dim3(32, 32, 4), 256, I8_SMEM>>>(
        q8l, k8h, sql, skh, S, 4096, 768,
        4096LL * 768, 4096LL * 768, 4096LL * 4096, 4096, 4096);
    wm_gemm<1, false, false, 2, false><<<dim3(32, 32, 4), 256, SMEM_TOTAL>>>(
        Qh, nullptr, Kh, nullptr, nullptr, S, nullptr, nullptr, nullptr, nullptr,
        4096, 768, 4096LL * 768, 4096LL * 768, 4096LL * 4096, nullptr);

    softmax_pair<<<16384, 256>>>(S, Ph, Pl);

    // attn@V: int8 lo-leg -> scratch (S), fp16 hi-leg accumulates
    quant_g<<<16384, 256>>>(Pl, p8, sp, 4096);
    i8_gemm<true><<<dim3(6, 32, 4), 256, I8_SMEM>>>(
        p8, vt8, sp, svt, S, 768, 4096,
        4096LL * 4096, 768LL * 4096, 4096LL * 768, 4096, 768);
    wm_gemm<1, false, false, 1, true><<<dim3(6, 32, 4), 256, SMEM_TOTAL>>>(
        Ph, nullptr, VTs, nullptr, nullptr, nullptr, NVh, NVl, nullptr, nullptr,
        768, 4096, 4096LL * 4096, 768LL * 4096, 4096LL * 768, S);

    // FFN1: int8 lo-leg -> scratch (S), fp16 hi-leg + bias + relu
    quant_g<<<16384, 256>>>(NVl, nv8, snv, 768);
    i8_gemm<true><<<dim3(24, 128, 1), 256, I8_SMEM>>>(
        nv8, w18, snv, sw1, S, 3072, 768, 0, 0, 0, 0, 0);
    wm_gemm<1, true, true, 1, true><<<dim3(24, 128, 1), 256, SMEM_TOTAL>>>(
        NVh, nullptr, W1s, nullptr, b1, nullptr, Hh, Hl, nullptr, nullptr,
        3072, 768, 0, 0, 0, S);

    // FFN2: int8 lo-leg -> scratch (S), fp16 hi-leg + bias, f32 out
    quant_g<<<16384, 256>>>(Hl, h8, sh, 3072);
    i8_gemm<true><<<dim3(6, 128, 1), 256, I8_SMEM>>>(
        h8, w28, sh, sw2, S, 768, 3072, 0, 0, 0, 0, 0);
    wm_gemm<1, true, false, 0, true><<<dim3(6, 128, 1), 256, SMEM_TOTAL>>>(
        Hh, nullptr, W2s, nullptr, b2, out, nullptr, nullptr, nullptr, nullptr,
        768, 3072, 0, 0, 0, S);
}

// round 13
// speedup vs baseline: 1.0539x; 1.0539x over previous
#include <cuda_runtime.h>
#include <cuda_fp16.h>
#include <stdint.h>

// ============================================================================
// GPT block, sm_100-safe mma.sync.
//   QKV      : fused 3-pass fp16 GEMM (Q,K pair out; V fp32 out)
//   scores   : fused dual-acc int8 (q8h*k8l & q8l*k8h) + fp16 Qh*Kh RMW
//   attn@V / FFN1 / FFN2 : int8 DOUBLE-LEVEL single-kernel GEMMs:
//       A = sa(a1 + a2/256), B = sb(b1 + b2/256)  (15-bit effective)
//       A@B = sa*sb*(a1b1 + (a1b2+a2b1)/256)  -> 3 int8 MMAs, 2 s32 acc sets
// ============================================================================

typedef __half h16;

// ---------------- helpers ----------------
__device__ __forceinline__ uint32_t smem_u32(const void* p) {
    uint32_t a;
    asm("{ .reg .u64 t; cvta.to.shared.u64 t, %1; cvt.u32.u64 %0, t; }"
        : "=r"(a) : "l"(p));
    return a;
}
__device__ __forceinline__ void cp16(uint32_t saddr, const void* g) {
    asm volatile("cp.async.cg.shared.global [%0], [%1], 16;"
                 :: "r"(saddr), "l"(g) : "memory");
}
#define CP_COMMIT() asm volatile("cp.async.commit_group;" ::: "memory")
#define CP_WAIT1()  asm volatile("cp.async.wait_group 1;" ::: "memory")

__device__ __forceinline__ void ldsm4(uint32_t* r, uint32_t a) {
    asm volatile("ldmatrix.sync.aligned.m8n8.x4.shared.b16 {%0,%1,%2,%3}, [%4];"
                 : "=r"(r[0]), "=r"(r[1]), "=r"(r[2]), "=r"(r[3]) : "r"(a));
}
__device__ __forceinline__ void mma16816(float* c, const uint32_t* a,
                                         const uint32_t* b) {
    asm volatile(
        "mma.sync.aligned.m16n8k16.row.col.f32.f16.f16.f32 "
        "{%0,%1,%2,%3}, {%4,%5,%6,%7}, {%8,%9}, {%0,%1,%2,%3};"
        : "+f"(c[0]), "+f"(c[1]), "+f"(c[2]), "+f"(c[3])
        : "r"(a[0]), "r"(a[1]), "r"(a[2]), "r"(a[3]), "r"(b[0]), "r"(b[1]));
}
__device__ __forceinline__ void mma_s8(int* c, const uint32_t* a,
                                       const uint32_t* b) {
    asm volatile(
        "mma.sync.aligned.m16n8k32.row.col.s32.s8.s8.s32 "
        "{%0,%1,%2,%3}, {%4,%5,%6,%7}, {%8,%9}, {%0,%1,%2,%3};"
        : "+r"(c[0]), "+r"(c[1]), "+r"(c[2]), "+r"(c[3])
        : "r"(a[0]), "r"(a[1]), "r"(a[2]), "r"(a[3]), "r"(b[0]), "r"(b[1]));
}

__device__ __forceinline__ uint32_t swz(int r, int s) {
    return (uint32_t)(r * 64 + ((s ^ ((r >> 1) & 3)) << 4));
}
__device__ __forceinline__ void split2h(float v, h16& h, h16& l) {
    h = __float2half(v);
    l = __float2half(v - __half2float(h));
}
__device__ __forceinline__ int clamp127(int x) {
    return x < -127 ? -127 : (x > 127 ? 127 : x);
}

// ---------------- scratch ----------------
__device__ h16 g_Xh[16384LL * 768], g_Xl[16384LL * 768];
__device__ h16 g_Wch[2304LL * 768], g_Wcl[2304LL * 768];
__device__ h16 g_Qh[4LL * 4096 * 768], g_Ql[4LL * 4096 * 768];
__device__ h16 g_Kh[4LL * 4096 * 768], g_Kl[4LL * 4096 * 768];
__device__ float g_Vf[4LL * 4096 * 768];
__device__ float g_VTf[4LL * 768 * 4096];
__device__ float g_S[4LL * 4096 * 4096];
__device__ h16 g_NVh[4LL * 4096 * 768], g_NVl[4LL * 4096 * 768];
__device__ h16 g_Hh[16384LL * 3072], g_Hl[16384LL * 3072];
// scores int8 corrections
__device__ char g_q8h[16384LL * 768], g_q8l[16384LL * 768];
__device__ char g_k8h[16384LL * 768], g_k8l[16384LL * 768];
__device__ float g_sqh[16384], g_sql[16384], g_skh[16384], g_skl[16384];
// double-level int8 operands
__device__ char g_p8a[16384LL * 4096], g_p8b[16384LL * 4096];
__device__ char g_vt8a[3072LL * 4096], g_vt8b[3072LL * 4096];
__device__ char g_nv8a[16384LL * 768], g_nv8b[16384LL * 768];
__device__ char g_h8a[16384LL * 3072], g_h8b[16384LL * 3072];
__device__ char g_w18a[3072 * 768], g_w18b[3072 * 768];
__device__ char g_w28a[768 * 3072], g_w28b[768 * 3072];
__device__ float g_sp[16384], g_svt[3072], g_snv[16384], g_sH[16384];
__device__ float g_sw1[3072], g_sw2[768];

// ---------------- fp16 GEMM (QKV route + scores hi-pass) ----------------
static constexpr int STAGE_BYTES = 32768;
static constexpr int SMEM_TOTAL  = 3 * STAGE_BYTES;

template <int PASSES>
__device__ __forceinline__ void load_stage(
    uint32_t so, int tid,
    const h16* __restrict__ Ah, const h16* __restrict__ Al,
    const h16* __restrict__ Bh, const h16* __restrict__ Bl,
    long long k0, int K)
{
    const int r = tid & 127, h = tid >> 7;
#pragma unroll
    for (int u = 0; u < 2; ++u) {
        const uint32_t d = swz(r, h * 2 + u);
        const long long g = (long long)r * K + k0 + (h * 2 + u) * 8;
        cp16(so + d,         Ah + g);
        if (PASSES >= 2) cp16(so + 8192 + d, Al + g);
        cp16(so + 16384 + d, Bh + g);
        if (PASSES == 3)  cp16(so + 24576 + d, Bl + g);
    }
}

// OM: 2 = f32 accumulate in-place, 3 = fused QKV routing
template <int PASSES, int OM>
__global__ __launch_bounds__(256, 2)
void wm_gemm(const h16* __restrict__ Ahi, const h16* __restrict__ Alo,
             const h16* __restrict__ Bhi, const h16* __restrict__ Blo,
             float* __restrict__ Cf, h16* __restrict__ Chi, h16* __restrict__ Clo,
             h16* __restrict__ C2hi, h16* __restrict__ C2lo,
             const int N, const int K,
             const long long bA, const long long bB, const long long bC)
{
    extern __shared__ __align__(128) char smem[];
    const uint32_t sb = smem_u32(smem);
    const int tid = threadIdx.x;
    const int wid = tid >> 5, lane = tid & 31;
    const int wm = wid >> 1, wn = wid & 1;
    const int lj = lane >> 3, lr = lane & 7;

    const long long bm = (long long)blockIdx.y * 128;
    const long long bn = (long long)blockIdx.x * 128;

    const h16* Ah = Ahi + (long long)blockIdx.z * bA + bm * K;
    const h16* Al = (PASSES >= 2) ? (Alo + (long long)blockIdx.z * bA + bm * K) : nullptr;
    const h16* Bh = Bhi + (long long)blockIdx.z * bB + bn * K;
    const h16* Bl = (PASSES == 3) ? (Blo + (long long)blockIdx.z * bB + bn * K) : nullptr;

    float acc[2][8][4];
#pragma unroll
    for (int i = 0; i < 2; ++i)
#pragma unroll
        for (int j = 0; j < 8; ++j)
#pragma unroll
            for (int t = 0; t < 4; ++t) acc[i][j][t] = 0.0f;

    const int NC = K / 32;
    load_stage<PASSES>(sb, tid, Ah, Al, Bh, Bl, 0, K);
    CP_COMMIT();
    load_stage<PASSES>(sb + STAGE_BYTES, tid, Ah, Al, Bh, Bl, 32, K);
    CP_COMMIT();

    const int arow = wm * 32 + ((lj & 1) << 3) + lr;
    const int aseg = lj >> 1;
    const int brow = wn * 64 + ((lj >> 1) << 3) + lr;
    const int bseg = lj & 1;

    int buf = 0;
    for (int c = 0; c < NC; ++c) {
        CP_WAIT1();
        __syncthreads();
        if (c + 2 < NC) {
            int nb = buf + 2; if (nb >= 3) nb -= 3;
            load_stage<PASSES>(sb + nb * STAGE_BYTES, tid, Ah, Al, Bh, Bl,
                               (long long)(c + 2) * 32, K);
        }
        CP_COMMIT();

        const uint32_t bb = sb + buf * STAGE_BYTES;
#pragma unroll
        for (int ks = 0; ks < 2; ++ks) {
            uint32_t Afh[2][4], Afl[2][4];
#pragma unroll
            for (int mt = 0; mt < 2; ++mt) {
                const uint32_t off = swz(arow + mt * 16, ks * 2 + aseg);
                ldsm4(Afh[mt], bb + off);
                if (PASSES >= 2) ldsm4(Afl[mt], bb + 8192 + off);
            }
#pragma unroll
            for (int ntp = 0; ntp < 4; ++ntp) {
                const uint32_t off = swz(brow + ntp * 16, ks * 2 + bseg);
                uint32_t Bfh[4];
                ldsm4(Bfh, bb + 16384 + off);
                uint32_t Bfl[4];
                if (PASSES == 3) ldsm4(Bfl, bb + 24576 + off);
#pragma unroll
                for (int mt = 0; mt < 2; ++mt)
#pragma unroll
                    for (int h = 0; h < 2; ++h) {
                        float* cc = acc[mt][ntp * 2 + h];
                        mma16816(cc, Afh[mt], &Bfh[h * 2]);
                        if (PASSES >= 2) mma16816(cc, Afl[mt], &Bfh[h * 2]);
                        if (PASSES == 3) mma16816(cc, Afh[mt], &Bfl[h * 2]);
                    }
            }
        }
        ++buf; if (buf == 3) buf = 0;
    }

    const long long zC = (long long)blockIdx.z * bC;
    const int rbase = (int)bm + wm * 32 + (lane >> 2);
    const int seg   = (OM == 3) ? (int)(bn / 768) : 0;
    const int cbase = (OM == 3)
        ? ((int)bn - seg * 768 + wn * 64 + (lane & 3) * 2)
        : ((int)bn + wn * 64 + (lane & 3) * 2);
    const int cstride = (OM == 3) ? 768 : N;

#pragma unroll
    for (int mt = 0; mt < 2; ++mt)
#pragma unroll
        for (int nt = 0; nt < 8; ++nt) {
            const int col = cbase + nt * 8;
#pragma unroll
            for (int rh = 0; rh < 2; ++rh) {
                const int row = rbase + mt * 16 + rh * 8;
                float v0 = acc[mt][nt][rh * 2 + 0];
                float v1 = acc[mt][nt][rh * 2 + 1];
                const long long o = zC + (long long)row * cstride + col;
                if (OM == 2) {
                    float2 t = *(const float2*)(Cf + o);
                    t.x += v0; t.y += v1;
                    *(float2*)(Cf + o) = t;
                } else {  // OM == 3: QKV routing
                    if (seg == 0) {
                        h16 h0, l0, h1, l1;
                        split2h(v0, h0, l0); split2h(v1, h1, l1);
                        *(__half2*)(Chi + o) = __halves2half2(h0, h1);
                        *(__half2*)(Clo + o) = __halves2half2(l0, l1);
                    } else if (seg == 1) {
                        h16 h0, l0, h1, l1;
                        split2h(v0, h0, l0); split2h(v1, h1, l1);
                        *(__half2*)(C2hi + o) = __halves2half2(h0, h1);
                        *(__half2*)(C2lo + o) = __halves2half2(l0, l1);
                    } else {
                        float2 w; w.x = v0; w.y = v1;
                        *(float2*)(Cf + o) = w;
                    }
                }
            }
        }
}

// ---------------- dual-accumulator int8 GEMM ----------------
// MODE 0: scores-corr: val = sa1*sb1*acc1 + sa2*sb2*acc2       -> f32 INIT
// MODE 1: double-lvl : val = sa1*sb1*(acc1 + acc2/256)         -> pair out
// MODE 2: double-lvl + bias + relu                             -> pair out
// MODE 3: double-lvl + bias                                    -> f32 out
static constexpr int I8D_STAGE = 32768;
static constexpr int I8D_SMEM  = 3 * I8D_STAGE;

__device__ __forceinline__ void i8d_load(uint32_t so, int tid,
    const char* __restrict__ A1, const char* __restrict__ A2,
    const char* __restrict__ B1, const char* __restrict__ B2,
    long long k0, int K)
{
    const int r = tid & 127, hf = tid >> 7;
#pragma unroll
    for (int u = 0; u < 2; ++u) {
        const int s = hf * 2 + u;
        const uint32_t d = swz(r, s);
        const long long g = (long long)r * K + k0 + s * 16;
        cp16(so + d,         A1 + g);
        cp16(so + 8192 + d,  A2 + g);
        cp16(so + 16384 + d, B1 + g);
        cp16(so + 24576 + d, B2 + g);
    }
}

template <int MODE>
__global__ __launch_bounds__(256, 1)
void i8d_gemm(const char* __restrict__ A1, const char* __restrict__ A2,
              const char* __restrict__ B1, const char* __restrict__ B2,
              const float* __restrict__ sa1, const float* __restrict__ sa2,
              const float* __restrict__ sb1, const float* __restrict__ sb2,
              const float* __restrict__ bias,
              float* __restrict__ Cf, h16* __restrict__ Chi, h16* __restrict__ Clo,
              const int N, const int K,
              const long long bA, const long long bB, const long long bC,
              const int sAz, const int sBz)
{
    extern __shared__ __align__(128) char smem[];
    const uint32_t sbase = smem_u32(smem);
    const int tid = threadIdx.x;
    const int wid = tid >> 5, lane = tid & 31;
    const int wm = wid >> 1, wn = wid & 1;
    const int lj = lane >> 3, lr = lane & 7;
    const int z = blockIdx.z;
    const long long bm = (long long)blockIdx.y * 128;
    const long long bn = (long long)blockIdx.x * 128;

    const char* A1b = A1 + (long long)z * bA + bm * K;
    const char* A2b = A2 + (long long)z * bA + bm * K;
    const char* B1b = B1 + (long long)z * bB + bn * K;
    const char* B2b = B2 + (long long)z * bB + bn * K;
    const float* sa1v = sa1 + (long long)z * sAz + bm;
    const float* sb1v = sb1 + (long long)z * sBz + bn;
    const float* sa2v = (MODE == 0) ? (sa2 + (long long)z * sAz + bm) : nullptr;
    const float* sb2v = (MODE == 0) ? (sb2 + (long long)z * sBz + bn) : nullptr;

    int acc1[2][8][4], acc2[2][8][4];
#pragma unroll
    for (int i = 0; i < 2; ++i)
#pragma unroll
        for (int j = 0; j < 8; ++j)
#pragma unroll
            for (int t = 0; t < 4; ++t) { acc1[i][j][t] = 0; acc2[i][j][t] = 0; }

    const int NC = K / 64;
    i8d_load(sbase, tid, A1b, A2b, B1b, B2b, 0, K);
    CP_COMMIT();
    i8d_load(sbase + I8D_STAGE, tid, A1b, A2b, B1b, B2b, 64, K);
    CP_COMMIT();

    // s8 fragment order == fp16 order (R9): row-block fastest for A
    const int arow = wm * 32 + ((lj & 1) << 3) + lr;
    const int aso  = lj >> 1;
    const int brow = wn * 64 + ((lj >> 1) << 3) + lr;
    const int bso  = lj & 1;

    int buf = 0;
    for (int c = 0; c < NC; ++c) {
        CP_WAIT1();
        __syncthreads();
        if (c + 2 < NC) {
            int nb = buf + 2; if (nb >= 3) nb -= 3;
            i8d_load(sbase + nb * I8D_STAGE, tid, A1b, A2b, B1b, B2b,
                     (long long)(c + 2) * 64, K);
        }
        CP_COMMIT();

        const uint32_t bb = sbase + buf * I8D_STAGE;
#pragma unroll
        for (int step = 0; step < 2; ++step) {
            uint32_t A1f[2][4], A2f[2][4];
#pragma unroll
            for (int mt = 0; mt < 2; ++mt) {
                const uint32_t off = swz(arow + mt * 16, step * 2 + aso);
                ldsm4(A1f[mt], bb + off);
                ldsm4(A2f[mt], bb + 8192 + off);
            }
#pragma unroll
            for (int ntp = 0; ntp < 4; ++ntp) {
                const uint32_t off = swz(brow + ntp * 16, step * 2 + bso);
                uint32_t B1f[4], B2f[4];
                ldsm4(B1f, bb + 16384 + off);
                ldsm4(B2f, bb + 24576 + off);
#pragma unroll
                for (int mt = 0; mt < 2; ++mt)
#pragma unroll
                    for (int h = 0; h < 2; ++h) {
                        int* c1 = acc1[mt][ntp * 2 + h];
                        int* c2 = acc2[mt][ntp * 2 + h];
                        mma_s8(c1, A1f[mt], &B1f[h * 2]);
                        if (MODE == 0) {
                            mma_s8(c2, A2f[mt], &B2f[h * 2]);
                        } else {
                            mma_s8(c2, A1f[mt], &B2f[h * 2]);
                            mma_s8(c2, A2f[mt], &B1f[h * 2]);
                        }
                    }
            }
        }
        ++buf; if (buf == 3) buf = 0;
    }

    // epilogue
    const int rb = wm * 32 + (lane >> 2);
    const int cb = wn * 64 + (lane & 3) * 2;
    const long long zC = (long long)z * bC;
#pragma unroll
    for (int mt = 0; mt < 2; ++mt)
#pragma unroll
        for (int rh = 0; rh < 2; ++rh) {
            const int lrw = rb + mt * 16 + rh * 8;
            const float sA1 = sa1v[lrw];
            const float sA2 = (MODE == 0) ? sa2v[lrw] : 0.f;
#pragma unroll
            for (int nt = 0; nt < 8; ++nt) {
                const int lc = cb + nt * 8;
                const int x1a = acc1[mt][nt][rh * 2 + 0];
                const int x1b = acc1[mt][nt][rh * 2 + 1];
                const int x2a = acc2[mt][nt][rh * 2 + 0];
                const int x2b = acc2[mt][nt][rh * 2 + 1];
                float v0, v1;
                if (MODE == 0) {
                    v0 = sA1 * sb1v[lc]     * (float)x1a + sA2 * sb2v[lc]     * (float)x2a;
                    v1 = sA1 * sb1v[lc + 1] * (float)x1b + sA2 * sb2v[lc + 1] * (float)x2b;
                } else {
                    v0 = sA1 * sb1v[lc]     * ((float)x1a + (float)x2a * 0.00390625f);
                    v1 = sA1 * sb1v[lc + 1] * ((float)x1b + (float)x2b * 0.00390625f);
                }
                if (MODE >= 2) {
                    v0 += bias[(int)bn + lc];
                    v1 += bias[(int)bn + lc + 1];
                }
                if (MODE == 2) { v0 = fmaxf(v0, 0.f); v1 = fmaxf(v1, 0.f); }
                const long long o = zC + (bm + lrw) * N + bn + lc;
                if (MODE == 0 || MODE == 3) {
                    float2 w; w.x = v0; w.y = v1;
                    *(float2*)(Cf + o) = w;
                } else {
                    h16 h0, l0, h1, l1;
                    split2h(v0, h0, l0); split2h(v1, h1, l1);
                    *(__half2*)(Chi + o) = __halves2half2(h0, h1);
                    *(__half2*)(Clo + o) = __halves2half2(l0, l1);
                }
            }
        }
}

// ---------------- per-row int8 quant of fp16 pair, L=768 (scores Q/K) --------
__global__ __launch_bounds__(256)
void quant_rows(const h16* __restrict__ Ah, const h16* __restrict__ Al,
                char* __restrict__ q8h, char* __restrict__ q8l,
                float* __restrict__ sh, float* __restrict__ sl)
{
    __shared__ float red[8][2];
    const long long row = blockIdx.x;
    const int tid = threadIdx.x, lane = tid & 31, warp = tid >> 5;
    const h16* ph = Ah + row * 768;
    const h16* pl = Al + row * 768;

    float vh[3], vl[3];
    float mh = 0.f, ml = 0.f;
#pragma unroll
    for (int i = 0; i < 3; ++i) {
        vh[i] = __half2float(ph[tid + i * 256]);
        vl[i] = __half2float(pl[tid + i * 256]);
        mh = fmaxf(mh, fabsf(vh[i]));
        ml = fmaxf(ml, fabsf(vl[i]));
    }
#pragma unroll
    for (int o = 16; o > 0; o >>= 1) {
        mh = fmaxf(mh, __shfl_xor_sync(0xffffffffu, mh, o));
        ml = fmaxf(ml, __shfl_xor_sync(0xffffffffu, ml, o));
    }
    if (lane == 0) { red[warp][0] = mh; red[warp][1] = ml; }
    __syncthreads();
    mh = red[0][0]; ml = red[0][1];
#pragma unroll
    for (int w = 1; w < 8; ++w) {
        mh = fmaxf(mh, red[w][0]);
        ml = fmaxf(ml, red[w][1]);
    }
    mh = fmaxf(mh, 1e-20f);
    ml = fmaxf(ml, 1e-20f);
    const float ih = 127.f / mh, il = 127.f / ml;
#pragma unroll
    for (int i = 0; i < 3; ++i) {
        q8h[row * 768 + tid + i * 256] = (char)__float2int_rn(vh[i] * ih);
        q8l[row * 768 + tid + i * 256] = (char)__float2int_rn(vl[i] * il);
    }
    if (tid == 0) { sh[row] = mh / 127.f; sl[row] = ml / 127.f; }
}

// ---------------- per-row double-level quant of fp16 pair ----------------
__global__ __launch_bounds__(256)
void quant_pd(const h16* __restrict__ Ah, const h16* __restrict__ Al,
              char* __restrict__ q1, char* __restrict__ q2,
              float* __restrict__ s, const int L)
{
    __shared__ float red[8];
    const long long row = blockIdx.x;
    const int tid = threadIdx.x, lane = tid & 31, warp = tid >> 5;
    const h16* ph = Ah + row * (long long)L;
    const h16* pl = Al + row * (long long)L;

    float m = 0.f;
    for (int i = tid; i < L; i += 256)
        m = fmaxf(m, fabsf(__half2float(ph[i]) + __half2float(pl[i])));
#pragma unroll
    for (int o = 16; o > 0; o >>= 1)
        m = fmaxf(m, __shfl_xor_sync(0xffffffffu, m, o));
    if (lane == 0) red[warp] = m;
    __syncthreads();
    m = red[0];
#pragma unroll
    for (int w = 1; w < 8; ++w) m = fmaxf(m, red[w]);
    m = fmaxf(m, 1e-20f);
    const float inv = 127.f / m;
    char* p1 = q1 + row * (long long)L;
    char* p2 = q2 + row * (long long)L;
    for (int i = tid; i < L; i += 256) {
        const float v = (__half2float(ph[i]) + __half2float(pl[i])) * inv;
        const int a = __float2int_rn(v);
        p1[i] = (char)a;
        p2[i] = (char)clamp127(__float2int_rn((v - (float)a) * 256.f));
    }
    if (tid == 0) s[row] = m / 127.f;
}

// ---------------- per-row double-level quant of fp32 rows ----------------
__global__ __launch_bounds__(256)
void quant_f32d(const float* __restrict__ A, char* __restrict__ q1,
                char* __restrict__ q2, float* __restrict__ s, const int L)
{
    __shared__ float red[8];
    const long long row = blockIdx.x;
    const int tid = threadIdx.x, lane = tid & 31, warp = tid >> 5;
    const float* p = A + row * (long long)L;

    float m = 0.f;
    for (int i = tid; i < L; i += 256)
        m = fmaxf(m, fabsf(p[i]));
#pragma unroll
    for (int o = 16; o > 0; o >>= 1)
        m = fmaxf(m, __shfl_xor_sync(0xffffffffu, m, o));
    if (lane == 0) red[warp] = m;
    __syncthreads();
    m = red[0];
#pragma unroll
    for (int w = 1; w < 8; ++w) m = fmaxf(m, red[w]);
    m = fmaxf(m, 1e-20f);
    const float inv = 127.f / m;
    char* p1 = q1 + row * (long long)L;
    char* p2 = q2 + row * (long long)L;
    for (int i = tid; i < L; i += 256) {
        const float v = p[i] * inv;
        const int a = __float2int_rn(v);
        p1[i] = (char)a;
        p2[i] = (char)clamp127(__float2int_rn((v - (float)a) * 256.f));
    }
    if (tid == 0) s[row] = m / 127.f;
}

// ---------------- fp32 -> (hi,lo) fp16 ----------------
__global__ __launch_bounds__(256)
void cvt_pair(const float* __restrict__ in, h16* __restrict__ hi,
              h16* __restrict__ lo, const long long n)
{
    const long long i = ((long long)blockIdx.x * 256 + threadIdx.x) * 4;
    if (i >= n) return;
    const float4 v = *(const float4*)(in + i);
    __align__(8) h16 h[4];
    __align__(8) h16 l[4];
    split2h(v.x, h[0], l[0]); split2h(v.y, h[1], l[1]);
    split2h(v.z, h[2], l[2]); split2h(v.w, h[3], l[3]);
    *(uint2*)(hi + i) = *(const uint2*)h;
    *(uint2*)(lo + i) = *(const uint2*)l;
}

// ---------------- V transpose: [b,4096,768]f32 -> [b,768,4096] fp32 ----------
__global__ __launch_bounds__(256)
void transpose_f32(const float* __restrict__ V, float* __restrict__ T)
{
    __shared__ float tile[32][33];
    const int b = blockIdx.z;
    const int e0 = blockIdx.x * 32;
    const int t0 = blockIdx.y * 32;
    const float* Vb = V + (long long)b * 4096 * 768;
    float* Tb = T + (long long)b * 768 * 4096;
    const int tx = threadIdx.x, ty = threadIdx.y;
#pragma unroll
    for (int j = 0; j < 32; j += 8)
        tile[ty + j][tx] = Vb[(long long)(t0 + ty + j) * 768 + e0 + tx];
    __syncthreads();
#pragma unroll
    for (int j = 0; j < 32; j += 8)
        Tb[(long long)(e0 + ty + j) * 4096 + t0 + tx] = tile[tx][ty + j];
}

// ---------------- softmax (rows of 4096) -> double-level int8 ----------------
__global__ __launch_bounds__(256)
void softmax_i8(const float* __restrict__ S, char* __restrict__ p8a,
                char* __restrict__ p8b, float* __restrict__ sp)
{
    __shared__ float red[8];
    const long long row = blockIdx.x;
    const float* p = S + row * 4096;
    const int tid = threadIdx.x, lane = tid & 31, warp = tid >> 5;

    float4 v[4];
#pragma unroll
    for (int i = 0; i < 4; ++i)
        v[i] = *(const float4*)(p + tid * 4 + i * 1024);

    float mx = -3.402823466e38f;
#pragma unroll
    for (int i = 0; i < 4; ++i)
        mx = fmaxf(mx, fmaxf(fmaxf(v[i].x, v[i].y), fmaxf(v[i].z, v[i].w)));
#pragma unroll
    for (int o = 16; o > 0; o >>= 1)
        mx = fmaxf(mx, __shfl_xor_sync(0xffffffffu, mx, o));
    if (lane == 0) red[warp] = mx;
    __syncthreads();
    float rowmax = red[0];
#pragma unroll
    for (int w = 1; w < 8; ++w) rowmax = fmaxf(rowmax, red[w]);
    __syncthreads();

    float sum = 0.0f;
#pragma unroll
    for (int i = 0; i < 4; ++i) {
        v[i].x = __expf(v[i].x - rowmax);
        v[i].y = __expf(v[i].y - rowmax);
        v[i].z = __expf(v[i].z - rowmax);
        v[i].w = __expf(v[i].w - rowmax);
        sum += (v[i].x + v[i].y) + (v[i].z + v[i].w);
    }
#pragma unroll
    for (int o = 16; o > 0; o >>= 1)
        sum += __shfl_xor_sync(0xffffffffu, sum, o);
    if (lane == 0) red[warp] = sum;
    __syncthreads();
    float rowsum = 0.0f;
#pragma unroll
    for (int w = 0; w < 8; ++w) rowsum += red[w];

    // max prob = 1/rowsum (max exp == 1) -> s1 = inv/127; q1 = rnd(127*exp)
#pragma unroll
    for (int i = 0; i < 4; ++i) {
        int q1[4], q2[4];
        const float e[4] = {v[i].x, v[i].y, v[i].z, v[i].w};
#pragma unroll
        for (int t = 0; t < 4; ++t) {
            const float u = 127.f * e[t];
            q1[t] = __float2int_rn(u);
            q2[t] = clamp127(__float2int_rn((u - (float)q1[t]) * 256.f));
        }
        const long long o = row * 4096 + tid * 4 + i * 1024;
        uint32_t w1 = ((uint32_t)(uint8_t)(char)q1[0])
                    | ((uint32_t)(uint8_t)(char)q1[1] << 8)
                    | ((uint32_t)(uint8_t)(char)q1[2] << 16)
                    | ((uint32_t)(uint8_t)(char)q1[3] << 24);
        uint32_t w2 = ((uint32_t)(uint8_t)(char)q2[0])
                    | ((uint32_t)(uint8_t)(char)q2[1] << 8)
                    | ((uint32_t)(uint8_t)(char)q2[2] << 16)
                    | ((uint32_t)(uint8_t)(char)q2[3] << 24);
        *(uint32_t*)(p8a + o) = w1;
        *(uint32_t*)(p8b + o) = w2;
    }
    if (tid == 0) sp[row] = (1.0f / rowsum) / 127.f;
}

// ---------------- host ----------------
extern "C" void kernel_launch(void* const* d_in, const int* in_sizes, int n_in,
                              void* d_out, int out_size)
{
    const float* X  = (const float*)d_in[0];
    const float* Wq = (const float*)d_in[1];
    const float* Wk = (const float*)d_in[2];
    const float* Wv = (const float*)d_in[3];
    const float* W1 = (const float*)d_in[4];
    const float* b1 = (const float*)d_in[5];
    const float* W2 = (const float*)d_in[6];
    const float* b2 = (const float*)d_in[7];
    float* out = (float*)d_out;

    h16 *Xh, *Xl, *Wch, *Wcl, *Qh, *Ql, *Kh, *Kl, *NVh, *NVl, *Hh, *Hl;
    float *Vf, *VTf, *S;
    char *q8h, *q8l, *k8h, *k8l;
    float *sqh, *sql, *skh, *skl;
    char *p8a, *p8b, *vt8a, *vt8b, *nv8a, *nv8b, *h8a, *h8b;
    char *w18a, *w18b, *w28a, *w28b;
    float *sp, *svt, *snv, *sH, *sw1, *sw2;
    cudaGetSymbolAddress((void**)&Xh, g_Xh);     cudaGetSymbolAddress((void**)&Xl, g_Xl);
    cudaGetSymbolAddress((void**)&Wch, g_Wch);   cudaGetSymbolAddress((void**)&Wcl, g_Wcl);
    cudaGetSymbolAddress((void**)&Qh, g_Qh);     cudaGetSymbolAddress((void**)&Ql, g_Ql);
    cudaGetSymbolAddress((void**)&Kh, g_Kh);     cudaGetSymbolAddress((void**)&Kl, g_Kl);
    cudaGetSymbolAddress((void**)&Vf, g_Vf);     cudaGetSymbolAddress((void**)&VTf, g_VTf);
    cudaGetSymbolAddress((void**)&S, g_S);
    cudaGetSymbolAddress((void**)&NVh, g_NVh);   cudaGetSymbolAddress((void**)&NVl, g_NVl);
    cudaGetSymbolAddress((void**)&Hh, g_Hh);     cudaGetSymbolAddress((void**)&Hl, g_Hl);
    cudaGetSymbolAddress((void**)&q8h, g_q8h);   cudaGetSymbolAddress((void**)&q8l, g_q8l);
    cudaGetSymbolAddress((void**)&k8h, g_k8h);   cudaGetSymbolAddress((void**)&k8l, g_k8l);
    cudaGetSymbolAddress((void**)&sqh, g_sqh);   cudaGetSymbolAddress((void**)&sql, g_sql);
    cudaGetSymbolAddress((void**)&skh, g_skh);   cudaGetSymbolAddress((void**)&skl, g_skl);
    cudaGetSymbolAddress((void**)&p8a, g_p8a);   cudaGetSymbolAddress((void**)&p8b, g_p8b);
    cudaGetSymbolAddress((void**)&vt8a, g_vt8a); cudaGetSymbolAddress((void**)&vt8b, g_vt8b);
    cudaGetSymbolAddress((void**)&nv8a, g_nv8a); cudaGetSymbolAddress((void**)&nv8b, g_nv8b);
    cudaGetSymbolAddress((void**)&h8a, g_h8a);   cudaGetSymbolAddress((void**)&h8b, g_h8b);
    cudaGetSymbolAddress((void**)&w18a, g_w18a); cudaGetSymbolAddress((void**)&w18b, g_w18b);
    cudaGetSymbolAddress((void**)&w28a, g_w28a); cudaGetSymbolAddress((void**)&w28b, g_w28b);
    cudaGetSymbolAddress((void**)&sp, g_sp);     cudaGetSymbolAddress((void**)&svt, g_svt);
    cudaGetSymbolAddress((void**)&snv, g_snv);   cudaGetSymbolAddress((void**)&sH, g_sH);
    cudaGetSymbolAddress((void**)&sw1, g_sw1);   cudaGetSymbolAddress((void**)&sw2, g_sw2);

    cudaFuncSetAttribute(wm_gemm<3, 3>,
                         cudaFuncAttributeMaxDynamicSharedMemorySize, SMEM_TOTAL);
    cudaFuncSetAttribute(wm_gemm<1, 2>,
                         cudaFuncAttributeMaxDynamicSharedMemorySize, SMEM_TOTAL);
    cudaFuncSetAttribute(i8d_gemm<0>,
                         cudaFuncAttributeMaxDynamicSharedMemorySize, I8D_SMEM);
    cudaFuncSetAttribute(i8d_gemm<1>,
                         cudaFuncAttributeMaxDynamicSharedMemorySize, I8D_SMEM);
    cudaFuncSetAttribute(i8d_gemm<2>,
                         cudaFuncAttributeMaxDynamicSharedMemorySize, I8D_SMEM);
    cudaFuncSetAttribute(i8d_gemm<3>,
                         cudaFuncAttributeMaxDynamicSharedMemorySize, I8D_SMEM);

    // 0-4 (launch #5 = QKV GEMM for the ncu window)
    cvt_pair<<<12288, 256>>>(X,  Xh,  Xl,  16384LL * 768);
    cvt_pair<<<576,  256>>>(Wq, Wch,              Wcl,              768LL * 768);
    cvt_pair<<<576,  256>>>(Wk, Wch + 768 * 768,  Wcl + 768 * 768,  768LL * 768);
    cvt_pair<<<576,  256>>>(Wv, Wch + 1536 * 768, Wcl + 1536 * 768, 768LL * 768);
    quant_f32d<<<3072, 256>>>(W1, w18a, w18b, sw1, 768);

    // fused QKV: Q,K pair out; V fp32 out
    wm_gemm<3, 3><<<dim3(18, 128, 1), 256, SMEM_TOTAL>>>(
        Xh, Xl, Wch, Wcl, Vf, Qh, Ql, Kh, Kl, 2304, 768, 0, 0, 0);

    quant_rows<<<16384, 256>>>(Qh, Ql, q8h, q8l, sqh, sql);
    quant_rows<<<16384, 256>>>(Kh, Kl, k8h, k8l, skh, skl);
    quant_f32d<<<768, 256>>>(W2, w28a, w28b, sw2, 3072);
    transpose_f32<<<dim3(24, 128, 4), dim3(32, 8)>>>(Vf, VTf);
    quant_f32d<<<3072, 256>>>(VTf, vt8a, vt8b, svt, 4096);

    // scores: fused dual int8 corrections (INIT S), then fp16 hi-pass RMW
    i8d_gemm<0><<<dim3(32, 32, 4), 256, I8D_SMEM>>>(
        q8h, q8l, k8l, k8h, sqh, sql, skl, skh, nullptr,
        S, nullptr, nullptr, 4096, 768,
        4096LL * 768, 4096LL * 768, 4096LL * 4096, 4096, 4096);
    wm_gemm<1, 2><<<dim3(32, 32, 4), 256, SMEM_TOTAL>>>(
        Qh, nullptr, Kh, nullptr, S, nullptr, nullptr, nullptr, nullptr,
        4096, 768, 4096LL * 768, 4096LL * 768, 4096LL * 4096);

    softmax_i8<<<16384, 256>>>(S, p8a, p8b, sp);

    // attn@V: double-level int8, pair out
    i8d_gemm<1><<<dim3(6, 32, 4), 256, I8D_SMEM>>>(
        p8a, p8b, vt8a, vt8b, sp, nullptr, svt, nullptr, nullptr,
        nullptr, NVh, NVl, 768, 4096,
        4096LL * 4096, 768LL * 4096, 4096LL * 768, 4096, 768);

    // FFN1: double-level int8 + bias + relu, pair out
    quant_pd<<<16384, 256>>>(NVh, NVl, nv8a, nv8b, snv, 768);
    i8d_gemm<2><<<dim3(24, 128, 1), 256, I8D_SMEM>>>(
        nv8a, nv8b, w18a, w18b, snv, nullptr, sw1, nullptr, b1,
        nullptr, Hh, Hl, 3072, 768, 0, 0, 0, 0, 0);

    // FFN2: double-level int8 + bias, fp32 out
    quant_pd<<<16384, 256>>>(Hh, Hl, h8a, h8b, sH, 3072);
    i8d_gemm<3><<<dim3(6, 128, 1), 256, I8D_SMEM>>>(
        h8a, h8b, w28a, w28b, sH, nullptr, sw2, nullptr, b2,
        out, nullptr, nullptr, 768, 3072, 0, 0, 0, 0, 0);
}